// round 8
// baseline (speedup 1.0000x reference)
#include <cuda_runtime.h>
#include <cstdint>

#define HGT 512
#define WID 512
#define NB 2
#define NCH 64
#define NPTS 131072
#define NMASK 131072

// Scratch via __device__ globals (allocations are forbidden).
__device__ __align__(16) float g_mask[NB * HGT * WID];
__device__ int g_mode[2];   // 0 = int64 rows, 1 = int32 rows, 2 = float32 rows

// ---------------------------------------------------------------------------
// Index-format detection + robust row loader
// ---------------------------------------------------------------------------
__device__ __forceinline__ int detect_mode(const void* p) {
    const unsigned* w = (const unsigned*)p;
    bool hi_zero = true;
#pragma unroll
    for (int k = 0; k < 16; ++k) hi_zero &= (w[2 * k + 1] == 0u);
    if (hi_zero) return 0;
    bool small = true;
#pragma unroll
    for (int k = 0; k < 16; ++k) small &= (w[k] < 0x10000u);
    return small ? 1 : 2;
}

__global__ void detect_kernel(const void* idx, const void* midx) {
    if (threadIdx.x == 0) g_mode[0] = detect_mode(idx);
    if (threadIdx.x == 1) g_mode[1] = detect_mode(midx);
}

__device__ __forceinline__ void load_row3(const void* p, int i, int mode,
                                          int& b, int& y, int& x) {
    if (mode == 0) {
        const long long* q = (const long long*)p + 3 * (size_t)i;
        b = (int)q[0]; y = (int)q[1]; x = (int)q[2];
    } else if (mode == 1) {
        const int* q = (const int*)p + 3 * (size_t)i;
        b = q[0]; y = q[1]; x = q[2];
    } else {
        const float* q = (const float*)p + 3 * (size_t)i;
        b = (int)q[0]; y = (int)q[1]; x = (int)q[2];
    }
    b = b < 0 ? 0 : (b > NB - 1 ? NB - 1 : b);
    y = y < 0 ? 0 : (y > HGT - 1 ? HGT - 1 : y);
    x = x < 0 ? 0 : (x > WID - 1 ? WID - 1 : x);
}

// ---------------------------------------------------------------------------
// Packed f32x2 helpers (sm_103a 2x fp32 path)
// ---------------------------------------------------------------------------
__device__ __forceinline__ unsigned long long fma2(unsigned long long a,
                                                   unsigned long long b,
                                                   unsigned long long c) {
    unsigned long long d;
    asm("fma.rn.f32x2 %0, %1, %2, %3;" : "=l"(d) : "l"(a), "l"(b), "l"(c));
    return d;
}
__device__ __forceinline__ unsigned long long splat2(float a) {
    unsigned long long d;
    unsigned int ai = __float_as_uint(a);
    asm("mov.b64 %0, {%1, %2};" : "=l"(d) : "r"(ai), "r"(ai));
    return d;
}

// ---------------------------------------------------------------------------
// Kernel 1: zero the dense accumulator (d_out) and the mask grid.
// ---------------------------------------------------------------------------
__global__ void zero_kernel(float4* __restrict__ out4, int n_out4) {
    int i = blockIdx.x * blockDim.x + threadIdx.x;
    float4 z = make_float4(0.f, 0.f, 0.f, 0.f);
    if (i < n_out4) out4[i] = z;
    const int n_mask4 = NB * HGT * WID / 4;
    if (i < n_mask4) reinterpret_cast<float4*>(g_mask)[i] = z;
}

// ---------------------------------------------------------------------------
// Kernel 2: scatter mask_values into the mask grid.
// ---------------------------------------------------------------------------
__global__ void mask_scatter_kernel(const void* __restrict__ mi,
                                    const float* __restrict__ mv) {
    int i = blockIdx.x * blockDim.x + threadIdx.x;
    if (i < NMASK) {
        int b, y, x;
        load_row3(mi, i, g_mode[1], b, y, x);
        atomicAdd(&g_mask[(b * HGT + y) * WID + x], mv[i]);
    }
}

// ---------------------------------------------------------------------------
// Kernel 3: fused per-tap GEMM (128 points x 64 out, K=64) + vector-red
// scatter. 128 threads = 16x8; thread (ty,tx) owns 8 m-rows x 8 channels.
//
// Raising arithmetic intensity vs R6: 64 outputs/thread -> 64 B smem per
// 128 FLOP per k (0.5 B/FLOP), dropping the smem-crossbar time to the FFMA2
// issue floor. A is k-major so As[k][ty*8..+7] loads as 4 pre-packed f32x2
// m-pairs (2 LDS.128, no splats); B takes 2 LDS.128 + 8 channel splats.
// ---------------------------------------------------------------------------
__global__ __launch_bounds__(128, 4) void conv_scatter_kernel(
    const float* __restrict__ values, const float* __restrict__ kern,
    const void* __restrict__ idx, float* __restrict__ dense) {
    __shared__ float As[64][132];   // k-major values tile (+4 pad), ~33 KB
    __shared__ float Bs[64][64];    // one tap's 64x64 kernel slice, 16 KB
    __shared__ int Pb[128], Py[128], Px[128];

    const int tid = threadIdx.x;
    const int m0 = blockIdx.x * 128;
    const int mode = g_mode[0];

    // Point coords first so their LDGs overlap the A staging below.
    for (int i = tid; i < 128; i += 128) {
        int b, y, x;
        load_row3(idx, m0 + i, mode, b, y, x);
        Pb[i] = b; Py[i] = y; Px[i] = x;
    }
    // Stage A transposed: coalesced float4 gmem reads, scalar smem stores.
    for (int i = tid; i < 128 * 16; i += 128) {
        int m = i >> 4;
        int c = (i & 15) << 2;
        float4 v = *reinterpret_cast<const float4*>(values + (size_t)(m0 + m) * NCH + c);
        As[c + 0][m] = v.x;
        As[c + 1][m] = v.y;
        As[c + 2][m] = v.z;
        As[c + 3][m] = v.w;
    }

    const int ty = tid >> 3;   // 0..15 -> 8 consecutive m-rows each
    const int tx = tid & 7;    // 0..7  -> 8 channels each

#pragma unroll 1
    for (int tap = 0; tap < 9; ++tap) {
        __syncthreads();
        const float4* bsrc = reinterpret_cast<const float4*>(kern + (size_t)tap * NCH * NCH);
        for (int i = tid; i < 64 * 16; i += 128)
            reinterpret_cast<float4*>(Bs)[i] = bsrc[i];
        __syncthreads();

        unsigned long long acc[4][8];   // [m-pair][channel]
#pragma unroll
        for (int mp = 0; mp < 4; ++mp)
#pragma unroll
            for (int n = 0; n < 8; ++n) acc[mp][n] = 0ull;

#pragma unroll 4
        for (int k = 0; k < 64; ++k) {
            // A: 8 consecutive m values as 4 pre-packed f32x2 pairs.
            ulonglong2 A0 = *reinterpret_cast<const ulonglong2*>(&As[k][ty * 8]);
            ulonglong2 A1 = *reinterpret_cast<const ulonglong2*>(&As[k][ty * 8 + 4]);
            unsigned long long am[4] = {A0.x, A0.y, A1.x, A1.y};
            // B: 8 channels via 2 LDS.128, then 8 splats.
            float4 b0 = *reinterpret_cast<const float4*>(&Bs[k][tx * 8]);
            float4 b1 = *reinterpret_cast<const float4*>(&Bs[k][tx * 8 + 4]);
            unsigned long long sb[8];
            sb[0] = splat2(b0.x); sb[1] = splat2(b0.y);
            sb[2] = splat2(b0.z); sb[3] = splat2(b0.w);
            sb[4] = splat2(b1.x); sb[5] = splat2(b1.y);
            sb[6] = splat2(b1.z); sb[7] = splat2(b1.w);
#pragma unroll
            for (int mp = 0; mp < 4; ++mp)
#pragma unroll
                for (int n = 0; n < 8; ++n)
                    acc[mp][n] = fma2(am[mp], sb[n], acc[mp][n]);
        }

        const int dy = tap / 3 - 1;
        const int dx = tap % 3 - 1;
#pragma unroll
        for (int mp = 0; mp < 4; ++mp) {
#pragma unroll
            for (int e = 0; e < 2; ++e) {
                int m = ty * 8 + mp * 2 + e;
                int sy = Py[m] + dy;
                sy = sy < 0 ? 0 : (sy > HGT - 1 ? HGT - 1 : sy);
                int sx = Px[m] + dx;
                sx = sx < 0 ? 0 : (sx > WID - 1 ? WID - 1 : sx);
                float* p = dense + ((((size_t)Pb[m] * HGT + sy) * WID + sx) * NCH) + tx * 8;
                float f[8];
#pragma unroll
                for (int n = 0; n < 8; ++n)
                    f[n] = (e == 0) ? __uint_as_float((unsigned int)acc[mp][n])
                                    : __uint_as_float((unsigned int)(acc[mp][n] >> 32));
                asm volatile("red.global.add.v4.f32 [%0], {%1, %2, %3, %4};"
                             :: "l"(p), "f"(f[0]), "f"(f[1]), "f"(f[2]), "f"(f[3])
                             : "memory");
                asm volatile("red.global.add.v4.f32 [%0], {%1, %2, %3, %4};"
                             :: "l"(p + 4), "f"(f[4]), "f"(f[5]), "f"(f[6]), "f"(f[7])
                             : "memory");
            }
        }
    }
}

// ---------------------------------------------------------------------------
// Kernel 4: epilogue  out = (dense + mask*bias) * mask   (in place on d_out)
// ---------------------------------------------------------------------------
__global__ void epilogue_kernel(float4* __restrict__ out4,
                                const float4* __restrict__ bias4) {
    int i = blockIdx.x * blockDim.x + threadIdx.x;
    float m = g_mask[i >> 4];
    float4 d = out4[i];
    float4 bv = __ldg(&bias4[i & 15]);
    d.x = (d.x + m * bv.x) * m;
    d.y = (d.y + m * bv.y) * m;
    d.z = (d.z + m * bv.z) * m;
    d.w = (d.w + m * bv.w) * m;
    out4[i] = d;
}

// ---------------------------------------------------------------------------
extern "C" void kernel_launch(void* const* d_in, const int* in_sizes, int n_in,
                              void* d_out, int out_size) {
    const float* values = nullptr;
    const float* kern = nullptr;
    const float* bias = nullptr;
    const float* mask_values = nullptr;
    const void* indices = nullptr;
    const void* mask_indices = nullptr;

    for (int i = 0; i < n_in; ++i) {
        int s = in_sizes[i];
        if (s == 8388608)      values = (const float*)d_in[i];
        else if (s == 36864)   kern = (const float*)d_in[i];
        else if (s == 64)      bias = (const float*)d_in[i];
        else if (s == 131072)  mask_values = (const float*)d_in[i];
        else if (s == 393216 || s == 786432) {
            if (!indices) indices = d_in[i];
            else          mask_indices = d_in[i];
        }
    }
    if (!values)       values       = (const float*)d_in[0];
    if (!kern)         kern         = (const float*)d_in[1];
    if (!bias)         bias         = (const float*)d_in[2];
    if (!mask_values)  mask_values  = (const float*)d_in[3];
    if (!indices)      indices      = d_in[4];
    if (!mask_indices) mask_indices = d_in[5];

    float* out = (float*)d_out;
    const int n_out4 = NB * HGT * WID * NCH / 4;  // 8388608

    detect_kernel<<<1, 32>>>(indices, mask_indices);
    zero_kernel<<<(n_out4 + 255) / 256, 256>>>((float4*)out, n_out4);
    mask_scatter_kernel<<<(NMASK + 255) / 256, 256>>>(mask_indices, mask_values);
    conv_scatter_kernel<<<NPTS / 128, 128>>>(values, kern, indices, out);
    epilogue_kernel<<<n_out4 / 256, 256>>>((float4*)out, (const float4*)bias);
}

// round 9
// speedup vs baseline: 1.1086x; 1.1086x over previous
#include <cuda_runtime.h>
#include <cstdint>

#define HGT 512
#define WID 512
#define NB 2
#define NCH 64
#define NPTS 131072
#define NMASK 131072

// Scratch via __device__ globals (allocations are forbidden).
__device__ __align__(16) float g_mask[NB * HGT * WID];
__device__ int g_mode[2];   // 0 = int64 rows, 1 = int32 rows, 2 = float32 rows

// ---------------------------------------------------------------------------
// Index-format detection + robust row loader
// ---------------------------------------------------------------------------
__device__ __forceinline__ int detect_mode(const void* p) {
    const unsigned* w = (const unsigned*)p;
    bool hi_zero = true;
#pragma unroll
    for (int k = 0; k < 16; ++k) hi_zero &= (w[2 * k + 1] == 0u);
    if (hi_zero) return 0;
    bool small = true;
#pragma unroll
    for (int k = 0; k < 16; ++k) small &= (w[k] < 0x10000u);
    return small ? 1 : 2;
}

__global__ void detect_kernel(const void* idx, const void* midx) {
    if (threadIdx.x == 0) g_mode[0] = detect_mode(idx);
    if (threadIdx.x == 1) g_mode[1] = detect_mode(midx);
}

__device__ __forceinline__ void load_row3(const void* p, int i, int mode,
                                          int& b, int& y, int& x) {
    if (mode == 0) {
        const long long* q = (const long long*)p + 3 * (size_t)i;
        b = (int)q[0]; y = (int)q[1]; x = (int)q[2];
    } else if (mode == 1) {
        const int* q = (const int*)p + 3 * (size_t)i;
        b = q[0]; y = q[1]; x = q[2];
    } else {
        const float* q = (const float*)p + 3 * (size_t)i;
        b = (int)q[0]; y = (int)q[1]; x = (int)q[2];
    }
    b = b < 0 ? 0 : (b > NB - 1 ? NB - 1 : b);
    y = y < 0 ? 0 : (y > HGT - 1 ? HGT - 1 : y);
    x = x < 0 ? 0 : (x > WID - 1 ? WID - 1 : x);
}

// ---------------------------------------------------------------------------
// Packed f32x2 helpers (sm_103a 2x fp32 path)
// ---------------------------------------------------------------------------
__device__ __forceinline__ unsigned long long fma2(unsigned long long a,
                                                   unsigned long long b,
                                                   unsigned long long c) {
    unsigned long long d;
    asm("fma.rn.f32x2 %0, %1, %2, %3;" : "=l"(d) : "l"(a), "l"(b), "l"(c));
    return d;
}
__device__ __forceinline__ unsigned long long splat2(float a) {
    unsigned long long d;
    unsigned int ai = __float_as_uint(a);
    asm("mov.b64 %0, {%1, %2};" : "=l"(d) : "r"(ai), "r"(ai));
    return d;
}

// ---------------------------------------------------------------------------
// Kernel 1: zero the dense accumulator (d_out) and the mask grid.
// ---------------------------------------------------------------------------
__global__ void zero_kernel(float4* __restrict__ out4, int n_out4) {
    int i = blockIdx.x * blockDim.x + threadIdx.x;
    float4 z = make_float4(0.f, 0.f, 0.f, 0.f);
    if (i < n_out4) out4[i] = z;
    const int n_mask4 = NB * HGT * WID / 4;
    if (i < n_mask4) reinterpret_cast<float4*>(g_mask)[i] = z;
}

// ---------------------------------------------------------------------------
// Kernel 2: scatter mask_values into the mask grid.
// ---------------------------------------------------------------------------
__global__ void mask_scatter_kernel(const void* __restrict__ mi,
                                    const float* __restrict__ mv) {
    int i = blockIdx.x * blockDim.x + threadIdx.x;
    if (i < NMASK) {
        int b, y, x;
        load_row3(mi, i, g_mode[1], b, y, x);
        atomicAdd(&g_mask[(b * HGT + y) * WID + x], mv[i]);
    }
}

// ---------------------------------------------------------------------------
// Kernel 3: fused per-tap GEMM (128 points x 64 out, K=64) + vector-red
// scatter. 256 threads = 16x16; thread (ty,tx) owns 8 m-rows x 4 channels.
// R6 shape (best) with occupancy forced to 4 CTAs/SM (reg cap 64): the
// kernel is latency-exposed at 3 CTAs, not smem- or issue-limited, so more
// warps close the gap to the ~135us FFMA2 pipe floor.
// ---------------------------------------------------------------------------
__global__ __launch_bounds__(256, 4) void conv_scatter_kernel(
    const float* __restrict__ values, const float* __restrict__ kern,
    const void* __restrict__ idx, float* __restrict__ dense) {
    __shared__ float As[64][132];   // k-major values tile (+4 pad), ~33 KB
    __shared__ float Bs[64][64];    // one tap's 64x64 kernel slice, 16 KB
    __shared__ int Pb[128], Py[128], Px[128];

    const int tid = threadIdx.x;
    const int m0 = blockIdx.x * 128;
    const int mode = g_mode[0];

    // Point coords first so their LDGs overlap the A staging below.
    for (int i = tid; i < 128; i += 256) {
        int b, y, x;
        load_row3(idx, m0 + i, mode, b, y, x);
        Pb[i] = b; Py[i] = y; Px[i] = x;
    }
    // Stage A transposed: coalesced float4 gmem reads, scalar smem stores.
    for (int i = tid; i < 128 * 16; i += 256) {
        int m = i >> 4;
        int c = (i & 15) << 2;
        float4 v = *reinterpret_cast<const float4*>(values + (size_t)(m0 + m) * NCH + c);
        As[c + 0][m] = v.x;
        As[c + 1][m] = v.y;
        As[c + 2][m] = v.z;
        As[c + 3][m] = v.w;
    }

    const int ty = tid >> 4;   // 0..15 -> 8 consecutive m-rows each
    const int tx = tid & 15;   // 0..15 -> 4 channels each

#pragma unroll 1
    for (int tap = 0; tap < 9; ++tap) {
        __syncthreads();
        const float4* bsrc = reinterpret_cast<const float4*>(kern + (size_t)tap * NCH * NCH);
        for (int i = tid; i < 64 * 16; i += 256)
            reinterpret_cast<float4*>(Bs)[i] = bsrc[i];
        __syncthreads();

        unsigned long long acc[4][4];   // [m-pair][channel]
#pragma unroll
        for (int mp = 0; mp < 4; ++mp)
#pragma unroll
            for (int n = 0; n < 4; ++n) acc[mp][n] = 0ull;

#pragma unroll 8
        for (int k = 0; k < 64; ++k) {
            // A: 8 consecutive m values as 4 pre-packed f32x2 pairs.
            ulonglong2 A0 = *reinterpret_cast<const ulonglong2*>(&As[k][ty * 8]);
            ulonglong2 A1 = *reinterpret_cast<const ulonglong2*>(&As[k][ty * 8 + 4]);
            // B: one LDS.128, then 4 channel splats.
            float4 b = *reinterpret_cast<const float4*>(&Bs[k][tx * 4]);
            unsigned long long sb0 = splat2(b.x), sb1 = splat2(b.y);
            unsigned long long sb2 = splat2(b.z), sb3 = splat2(b.w);
            acc[0][0] = fma2(A0.x, sb0, acc[0][0]);
            acc[0][1] = fma2(A0.x, sb1, acc[0][1]);
            acc[0][2] = fma2(A0.x, sb2, acc[0][2]);
            acc[0][3] = fma2(A0.x, sb3, acc[0][3]);
            acc[1][0] = fma2(A0.y, sb0, acc[1][0]);
            acc[1][1] = fma2(A0.y, sb1, acc[1][1]);
            acc[1][2] = fma2(A0.y, sb2, acc[1][2]);
            acc[1][3] = fma2(A0.y, sb3, acc[1][3]);
            acc[2][0] = fma2(A1.x, sb0, acc[2][0]);
            acc[2][1] = fma2(A1.x, sb1, acc[2][1]);
            acc[2][2] = fma2(A1.x, sb2, acc[2][2]);
            acc[2][3] = fma2(A1.x, sb3, acc[2][3]);
            acc[3][0] = fma2(A1.y, sb0, acc[3][0]);
            acc[3][1] = fma2(A1.y, sb1, acc[3][1]);
            acc[3][2] = fma2(A1.y, sb2, acc[3][2]);
            acc[3][3] = fma2(A1.y, sb3, acc[3][3]);
        }

        const int dy = tap / 3 - 1;
        const int dx = tap % 3 - 1;
#pragma unroll
        for (int mp = 0; mp < 4; ++mp) {
#pragma unroll
            for (int e = 0; e < 2; ++e) {
                int m = ty * 8 + mp * 2 + e;
                int sy = Py[m] + dy;
                sy = sy < 0 ? 0 : (sy > HGT - 1 ? HGT - 1 : sy);
                int sx = Px[m] + dx;
                sx = sx < 0 ? 0 : (sx > WID - 1 ? WID - 1 : sx);
                float* p = dense + ((((size_t)Pb[m] * HGT + sy) * WID + sx) * NCH) + tx * 4;
                float f0, f1, f2, f3;
                if (e == 0) {
                    f0 = __uint_as_float((unsigned int)acc[mp][0]);
                    f1 = __uint_as_float((unsigned int)acc[mp][1]);
                    f2 = __uint_as_float((unsigned int)acc[mp][2]);
                    f3 = __uint_as_float((unsigned int)acc[mp][3]);
                } else {
                    f0 = __uint_as_float((unsigned int)(acc[mp][0] >> 32));
                    f1 = __uint_as_float((unsigned int)(acc[mp][1] >> 32));
                    f2 = __uint_as_float((unsigned int)(acc[mp][2] >> 32));
                    f3 = __uint_as_float((unsigned int)(acc[mp][3] >> 32));
                }
                asm volatile("red.global.add.v4.f32 [%0], {%1, %2, %3, %4};"
                             :: "l"(p), "f"(f0), "f"(f1), "f"(f2), "f"(f3)
                             : "memory");
            }
        }
    }
}

// ---------------------------------------------------------------------------
// Kernel 4: epilogue  out = (dense + mask*bias) * mask   (in place on d_out)
// ---------------------------------------------------------------------------
__global__ void epilogue_kernel(float4* __restrict__ out4,
                                const float4* __restrict__ bias4) {
    int i = blockIdx.x * blockDim.x + threadIdx.x;
    float m = g_mask[i >> 4];
    float4 d = out4[i];
    float4 bv = __ldg(&bias4[i & 15]);
    d.x = (d.x + m * bv.x) * m;
    d.y = (d.y + m * bv.y) * m;
    d.z = (d.z + m * bv.z) * m;
    d.w = (d.w + m * bv.w) * m;
    out4[i] = d;
}

// ---------------------------------------------------------------------------
extern "C" void kernel_launch(void* const* d_in, const int* in_sizes, int n_in,
                              void* d_out, int out_size) {
    const float* values = nullptr;
    const float* kern = nullptr;
    const float* bias = nullptr;
    const float* mask_values = nullptr;
    const void* indices = nullptr;
    const void* mask_indices = nullptr;

    for (int i = 0; i < n_in; ++i) {
        int s = in_sizes[i];
        if (s == 8388608)      values = (const float*)d_in[i];
        else if (s == 36864)   kern = (const float*)d_in[i];
        else if (s == 64)      bias = (const float*)d_in[i];
        else if (s == 131072)  mask_values = (const float*)d_in[i];
        else if (s == 393216 || s == 786432) {
            if (!indices) indices = d_in[i];
            else          mask_indices = d_in[i];
        }
    }
    if (!values)       values       = (const float*)d_in[0];
    if (!kern)         kern         = (const float*)d_in[1];
    if (!bias)         bias         = (const float*)d_in[2];
    if (!mask_values)  mask_values  = (const float*)d_in[3];
    if (!indices)      indices      = d_in[4];
    if (!mask_indices) mask_indices = d_in[5];

    float* out = (float*)d_out;
    const int n_out4 = NB * HGT * WID * NCH / 4;  // 8388608

    detect_kernel<<<1, 32>>>(indices, mask_indices);
    zero_kernel<<<(n_out4 + 255) / 256, 256>>>((float4*)out, n_out4);
    mask_scatter_kernel<<<(NMASK + 255) / 256, 256>>>(mask_indices, mask_values);
    conv_scatter_kernel<<<NPTS / 128, 256>>>(values, kern, indices, out);
    epilogue_kernel<<<n_out4 / 256, 256>>>((float4*)out, (const float4*)bias);
}